// round 6
// baseline (speedup 1.0000x reference)
#include <cuda_runtime.h>
#include <math.h>

#define NROWS   65536
#define DDIM    64
#define NTILE   1024          /* NROWS / 64 */
#define PBLK    148           /* persistent blocks, 1 per SM */
#define NTHR    512
#define NSTEPS  128
#define TSZ     4096          /* 64*64 floats per tile */

/* shared memory layout (float offsets) */
#define OFF_SB    0            /* 64   : bias                          */
#define OFF_CTL   64           /* 16   : control broadcast             */
#define OFF_W2    80           /* 4096 : W repacked (k-pair major)     */
#define OFF_SYI0  4176         /* 4096 : stage input buf 0 (+reduce)   */
#define OFF_SYI1  8272         /* 4096 : stage input buf 1             */
#define OFF_SK2   12368        /* 5*4096 : k2..k6 (same-thread access) */
#define SMEM_FLOATS 32848
#define SMEM_BYTES  (SMEM_FLOATS * 4)

typedef unsigned long long ull;

/* ---------------- persistent device state (no allocations) ---------------- */
__device__ float  g_Ya[NROWS * DDIM];
__device__ float  g_Yb[NROWS * DDIM];
__device__ float  g_Ka[NROWS * DDIM];
__device__ float  g_Kb[NROWS * DDIM];
__device__ double g_part[2][PBLK];
__device__ unsigned g_count;
__device__ unsigned g_release;

/* Dormand-Prince A coefficients (exact float32 of rationals) */
__constant__ float cA[6][6] = {
  { (float)(1.0/5.0), 0.f, 0.f, 0.f, 0.f, 0.f },
  { (float)(3.0/40.0), (float)(9.0/40.0), 0.f, 0.f, 0.f, 0.f },
  { (float)(44.0/45.0), (float)(-56.0/15.0), (float)(32.0/9.0), 0.f, 0.f, 0.f },
  { (float)(19372.0/6561.0), (float)(-25360.0/2187.0), (float)(64448.0/6561.0), (float)(-212.0/729.0), 0.f, 0.f },
  { (float)(9017.0/3168.0), (float)(-355.0/33.0), (float)(46732.0/5247.0), (float)(49.0/176.0), (float)(-5103.0/18656.0), 0.f },
  { (float)(35.0/384.0), 0.f, (float)(500.0/1113.0), (float)(125.0/192.0), (float)(-2187.0/6784.0), (float)(11.0/84.0) },
};

union F4U {
  float v[4];
  ull   q[2];
  float4 f4;
};

__device__ __forceinline__ F4U ld4u(const float* p) { F4U r; r.f4 = *(const float4*)p; return r; }
__device__ __forceinline__ void st4u(float* p, const F4U a) { *(float4*)p = a.f4; }

/* packed fp32x2 ops (Blackwell) */
__device__ __forceinline__ ull fma2(ull a, ull b, ull c) {
  ull d;
  asm("fma.rn.f32x2 %0, %1, %2, %3;" : "=l"(d) : "l"(a), "l"(b), "l"(c));
  return d;
}
__device__ __forceinline__ ull mul2(ull a, ull b) {
  ull d;
  asm("mul.rn.f32x2 %0, %1, %2;" : "=l"(d) : "l"(a), "l"(b));
  return d;
}
__device__ __forceinline__ ull pack2(float x) {
  ull d;
  asm("mov.b64 %0, {%1, %1};" : "=l"(d) : "f"(x));
  return d;
}
__device__ __forceinline__ void unpack2(ull v, float& lo, float& hi) {
  asm("mov.b64 {%0, %1}, %2;" : "=f"(lo), "=f"(hi) : "l"(v));
}

/* fast sin: args O(1..10); abs err ~2^-21, far below 1e-3 tolerance */
__device__ __forceinline__ float fsin(float x) {
  float r;
  asm("sin.approx.f32 %0, %1;" : "=f"(r) : "f"(x));
  return r;
}

/* 2x4-output 64-k GEMM via fma.rn.f32x2.
   Warp covers a 16x16 sub-tile (rows wr*16.., cols wc*16..): minimal unique
   smem traffic. a-rows are XOR-swizzled by chunk: real chunk c of row r is
   stored at chunk c ^ ((r>>1)&7); 8 lr groups per warp then read 8 distinct
   chunk slots per k4 -> 128B-unique, conflict-free wavefronts. */
__device__ __forceinline__ void gemm64_r2(const float* __restrict__ sa,
                                          const float* __restrict__ sW2,
                                          int r0, int swz, int cbg, float accf[2][4]) {
  ull acc[2][4];
#pragma unroll
  for (int i = 0; i < 2; ++i)
#pragma unroll
    for (int j = 0; j < 4; ++j) acc[i][j] = 0ull;

#pragma unroll
  for (int k4 = 0; k4 < 16; ++k4) {
    const int ck = (k4 ^ swz) * 4;      /* swizzled address of real chunk k4 */
    ulonglong2 av[2];
#pragma unroll
    for (int i = 0; i < 2; ++i)
      av[i] = *(const ulonglong2*)(sa + (r0 + i) * DDIM + ck);
#pragma unroll
    for (int hh = 0; hh < 2; ++hh) {
      const int k2 = k4 * 2 + hh;
      ulonglong2 w01 = *(const ulonglong2*)(sW2 + k2 * 128 + cbg * 4);
      ulonglong2 w23 = *(const ulonglong2*)(sW2 + k2 * 128 + 64 + cbg * 4);
#pragma unroll
      for (int i = 0; i < 2; ++i) {
        ull a = hh ? av[i].y : av[i].x;
        acc[i][0] = fma2(a, w01.x, acc[i][0]);
        acc[i][1] = fma2(a, w01.y, acc[i][1]);
        acc[i][2] = fma2(a, w23.x, acc[i][2]);
        acc[i][3] = fma2(a, w23.y, acc[i][3]);
      }
    }
  }
#pragma unroll
  for (int i = 0; i < 2; ++i)
#pragma unroll
    for (int j = 0; j < 4; ++j) {
      float lo, hi; unpack2(acc[i][j], lo, hi);
      accf[i][j] = lo + hi;
    }
}

__global__ void init_kernel() { g_count = 0u; g_release = 0u; }

/* ---------------- the whole solve in one persistent kernel ---------------- */
__global__ void __launch_bounds__(NTHR, 1) ode_kernel(const float* __restrict__ x,
                                                      const float* __restrict__ W,
                                                      const float* __restrict__ b,
                                                      float* __restrict__ out) {
  extern __shared__ float sm[];
  float* sb   = sm + OFF_SB;
  float* sW2  = sm + OFF_W2;
  float* syi0 = sm + OFF_SYI0;
  float* syi1 = sm + OFF_SYI1;
  float* sk2  = sm + OFF_SK2;  /* slot m holds k_{m+2}; same-thread, swizzled */

  const int tid = threadIdx.x, bid = blockIdx.x;
  /* 16x16 warp tiles: 4x4 warp grid over the 64x64 tile */
  const int wid = tid >> 5, lane = tid & 31;
  const int wr = wid >> 2, wc = wid & 3;
  const int lr = lane >> 2;           /* 0..7 row-pair within warp  */
  const int lc = lane & 3;            /* 0..3 col-group within warp */
  const int r0  = wr * 16 + lr * 2;   /* rows r0, r0+1 */
  const int cbg = wc * 4 + lc;        /* global col-group, j = cbg*4.. */
  const int swz = lr;                 /* == (r0>>1)&7 for both rows   */
  const int o0s = r0 * DDIM + ((cbg ^ swz) * 4);   /* swizzled smem offsets */
  const int o1s = o0s + DDIM;
  const int og0 = r0 * DDIM + cbg * 4;             /* global (real) offsets */
  const int og1 = og0 + DDIM;

  if (tid < 16) st4u(&sb[tid * 4], ld4u(&b[tid * 4]));
  /* repack W into k-pair-major layout (validated R3-R5) */
  for (int p = tid; p < 2048; p += NTHR) {
    const int k2 = p >> 6, j = p & 63;
    const int cbb = j >> 2, jr = j & 3;
    const int pos = k2 * 128 + ((jr >= 2) ? 64 : 0) + cbb * 4 + (jr & 1) * 2;
    sW2[pos]     = W[j * DDIM + 2 * k2];
    sW2[pos + 1] = W[j * DDIM + 2 * k2 + 1];
  }
  __syncthreads();
  const F4U bb = ld4u(&sb[cbg * 4]);

  /* prologue: Ya = x ; Ka = k1 = f(x) */
  for (int tile = bid; tile < NTILE; tile += PBLK) {
    const size_t base = (size_t)tile * TSZ;
    for (int i = tid; i < TSZ / 4; i += NTHR) {
      const int r = i >> 4, c = i & 15;
      F4U v = ld4u(&x[base + i * 4]);
      st4u(&syi0[r * DDIM + ((c ^ ((r >> 1) & 7)) * 4)], v);
      st4u(&g_Ya[base + i * 4], v);
    }
    __syncthreads();
    float acc[2][4];
    gemm64_r2(syi0, sW2, r0, swz, cbg, acc);
#pragma unroll
    for (int i = 0; i < 2; ++i) {
      F4U kv;
#pragma unroll
      for (int j = 0; j < 4; ++j) kv.v[j] = fsin(-(acc[i][j] + bb.v[j]));
      st4u(&g_Ka[base + (i ? og1 : og0)], kv);
    }
    __syncthreads();
  }

  float t = 0.0f, h = 0.01f, h_eff = 0.01f;
  int sel = 0, done = 0;
  unsigned nbar = 0;

  const float E0 = (float)(71.0 / 57600.0);
  const float E2 = (float)(-71.0 / 16695.0);
  const float E3 = (float)(71.0 / 1920.0);
  const float E4 = (float)(-17253.0 / 339200.0);
  const float E5 = (float)(22.0 / 525.0);
  const float E6 = (float)(-1.0 / 40.0);
  const float ATOL = 1e-5f, RTOL = 1e-5f;

  for (int step = 0; step < NSTEPS; ++step) {
    if (done) break;
    const float* __restrict__ Yg = sel ? g_Yb : g_Ya;
    const float* __restrict__ Kg = sel ? g_Kb : g_Ka;
    float* __restrict__ Yo = sel ? g_Ya : g_Yb;
    float* __restrict__ Ko = sel ? g_Ka : g_Kb;
    const ull h2 = pack2(h_eff);

    double lsum = 0.0;
    for (int tile = bid; tile < NTILE; tile += PBLK) {
      const size_t base = (size_t)tile * TSZ;
      F4U yv[2], k1v[2], k7v[2], y5v[2];
      yv[0]  = ld4u(&Yg[base + og0]); yv[1]  = ld4u(&Yg[base + og1]);
      k1v[0] = ld4u(&Kg[base + og0]); k1v[1] = ld4u(&Kg[base + og1]);

#pragma unroll
      for (int st = 1; st <= 6; ++st) {
        float* syiW = (st & 1) ? syi1 : syi0;
        const ull c1 = pack2(cA[st - 1][0]);
#pragma unroll
        for (int i = 0; i < 2; ++i) {
          const int os = i ? o1s : o0s;
          ull s0 = mul2(c1, k1v[i].q[0]);
          ull s1 = mul2(c1, k1v[i].q[1]);
#pragma unroll
          for (int m = 0; m < 5; ++m) {
            if (m + 2 <= st) {
              const ull cm = pack2(cA[st - 1][m + 1]);
              F4U kv = ld4u(&sk2[m * TSZ + os]);
              s0 = fma2(cm, kv.q[0], s0);
              s1 = fma2(cm, kv.q[1], s1);
            }
          }
          F4U yiv;
          yiv.q[0] = fma2(h2, s0, yv[i].q[0]);
          yiv.q[1] = fma2(h2, s1, yv[i].q[1]);
          st4u(&syiW[os], yiv);
          if (st == 6) { y5v[i] = yiv; st4u(&Yo[base + (i ? og1 : og0)], yiv); }
        }
        __syncthreads();   /* stage-input buffer visible to all */

        float acc[2][4];
        gemm64_r2(syiW, sW2, r0, swz, cbg, acc);

        if (st < 6) {
#pragma unroll
          for (int i = 0; i < 2; ++i) {
            F4U kv;
#pragma unroll
            for (int j = 0; j < 4; ++j) kv.v[j] = fsin(-(acc[i][j] + bb.v[j]));
            st4u(&sk2[(st - 1) * TSZ + (i ? o1s : o0s)], kv);  /* same-thread */
          }
        } else {
#pragma unroll
          for (int i = 0; i < 2; ++i)
#pragma unroll
            for (int j = 0; j < 4; ++j) k7v[i].v[j] = fsin(-(acc[i][j] + bb.v[j]));
        }
        /* no second sync: buffer st+2 reuses only after stage st+1's sync */
      }

      /* error accumulation + FSAL k7 -> next k1 (own elements only) */
#pragma unroll
      for (int i = 0; i < 2; ++i) {
        const int os = i ? o1s : o0s;
        F4U k3 = ld4u(&sk2[1 * TSZ + os]);
        F4U k4 = ld4u(&sk2[2 * TSZ + os]);
        F4U k5 = ld4u(&sk2[3 * TSZ + os]);
        F4U k6 = ld4u(&sk2[4 * TSZ + os]);
        st4u(&Ko[base + (i ? og1 : og0)], k7v[i]);
#pragma unroll
        for (int j = 0; j < 4; ++j) {
          float e = E0 * k1v[i].v[j];
          e = fmaf(E2, k3.v[j], e);
          e = fmaf(E3, k4.v[j], e);
          e = fmaf(E4, k5.v[j], e);
          e = fmaf(E5, k6.v[j], e);
          e = fmaf(E6, k7v[i].v[j], e);
          e *= h_eff;
          float scale = fmaf(RTOL, fmaxf(fabsf(yv[i].v[j]), fabsf(y5v[i].v[j])), ATOL);
          float r = e / scale;
          lsum += (double)(r * r);
        }
      }
      __syncthreads();   /* protect syi buffers before next tile */
    }

    /* deterministic block reduce (reuse syi0 region as doubles) */
    double* sdd = (double*)(sm + OFF_SYI0);
    sdd[tid] = lsum;
    __syncthreads();
#pragma unroll
    for (int off = NTHR / 2; off > 0; off >>= 1) {
      if (tid < off) sdd[tid] += sdd[tid + off];
      __syncthreads();
    }
    const int par = step & 1;
    if (tid == 0) g_part[par][bid] = sdd[0];

    /* grid barrier + fused control */
    ++nbar;
    if (tid == 0) {
      __threadfence();
      unsigned old = atomicAdd(&g_count, 1u);
      if (old == PBLK - 1) {
        atomicExch(&g_count, 0u);
        __threadfence();
        atomicExch(&g_release, nbar);
      } else {
        while (*((volatile unsigned*)&g_release) < nbar) { }
      }
      __threadfence();
      double s = 0.0;
      for (int i2 = 0; i2 < PBLK; ++i2) s += *((volatile double*)&g_part[par][i2]);
      sm[OFF_CTL] = sqrtf((float)(s / (double)((double)NROWS * (double)DDIM)));
    }
    __syncthreads();
    const float err_norm = sm[OFF_CTL];
    __syncthreads();

    /* exact reference control law (redundant in every thread) */
    const int accept = (err_norm <= 1.0f);
    if (accept) { t += h_eff; sel ^= 1; }
    float factor = 0.9f * powf(fmaxf(err_norm, 1e-10f), -0.2f);
    factor = fminf(fmaxf(factor, 0.2f), 10.0f);
    h = h_eff * factor;
    const float remaining = 5.0f - t;
    done = (remaining <= 0.0f) ? 1 : 0;
    h_eff = fminf(h, fmaxf(remaining, 1e-12f));
  }

  /* write accepted buffer to output */
  const float* __restrict__ Yf = sel ? g_Yb : g_Ya;
  for (int tile = bid; tile < NTILE; tile += PBLK) {
    const size_t base = (size_t)tile * TSZ;
    for (int i = tid; i < TSZ / 4; i += NTHR)
      st4u(&out[base + i * 4], ld4u(&Yf[base + i * 4]));
  }
}

extern "C" void kernel_launch(void* const* d_in, const int* in_sizes, int n_in,
                              void* d_out, int out_size) {
  const float* x = (const float*)d_in[0];
  const float* W = (const float*)d_in[1];
  const float* b = (const float*)d_in[2];
  float* out = (float*)d_out;

  cudaFuncSetAttribute(ode_kernel, cudaFuncAttributeMaxDynamicSharedMemorySize, SMEM_BYTES);

  init_kernel<<<1, 1>>>();
  ode_kernel<<<PBLK, NTHR, SMEM_BYTES>>>(x, W, b, out);
}

// round 7
// speedup vs baseline: 1.2071x; 1.2071x over previous
#include <cuda_runtime.h>
#include <math.h>

#define NROWS   65536
#define DDIM    64
#define NTILE   1024          /* NROWS / 64 */
#define PBLK    148           /* persistent blocks, 1 per SM */
#define NTHR    512
#define HTHR    256           /* half-block worker size */
#define NSTEPS  128
#define TSZ     4096          /* 64*64 floats per tile */

/* shared memory layout (float offsets) */
#define OFF_SB    0            /* 64 : bias */
#define OFF_CLAIM 64           /* 2 unsigned claim slots (+pad) */
#define OFF_W2    80           /* 4096 : W repacked */
#define OFF_H0    4176         /* per-half regions */
#define H_STRIDE  24592        /* syi 4096 + sk 20480 + red 16 */
#define H_SYI     0
#define H_SK      4096         /* 5 slots (k2..k6) x 4096 */
#define H_RED     24576        /* 8 doubles */
#define SMEM_FLOATS (OFF_H0 + 2 * H_STRIDE)
#define SMEM_BYTES  (SMEM_FLOATS * 4)

typedef unsigned long long ull;

/* ---------------- persistent device state (no allocations) ---------------- */
__device__ float    g_Ya[NROWS * DDIM];
__device__ float    g_Yb[NROWS * DDIM];
__device__ float    g_Ka[NROWS * DDIM];
__device__ float    g_Kb[NROWS * DDIM];
__device__ double   g_tpart[NTILE];       /* per-tile error partials (deterministic) */
__device__ unsigned g_tctr[NSTEPS];       /* per-step work-steal counters */
__device__ unsigned g_count;
__device__ unsigned g_release;

/* Dormand-Prince A coefficients (exact float32 of rationals) */
__constant__ float cA[6][6] = {
  { (float)(1.0/5.0), 0.f, 0.f, 0.f, 0.f, 0.f },
  { (float)(3.0/40.0), (float)(9.0/40.0), 0.f, 0.f, 0.f, 0.f },
  { (float)(44.0/45.0), (float)(-56.0/15.0), (float)(32.0/9.0), 0.f, 0.f, 0.f },
  { (float)(19372.0/6561.0), (float)(-25360.0/2187.0), (float)(64448.0/6561.0), (float)(-212.0/729.0), 0.f, 0.f },
  { (float)(9017.0/3168.0), (float)(-355.0/33.0), (float)(46732.0/5247.0), (float)(49.0/176.0), (float)(-5103.0/18656.0), 0.f },
  { (float)(35.0/384.0), 0.f, (float)(500.0/1113.0), (float)(125.0/192.0), (float)(-2187.0/6784.0), (float)(11.0/84.0) },
};

union F4U {
  float v[4];
  ull   q[2];
  float4 f4;
};

__device__ __forceinline__ F4U ld4u(const float* p) { F4U r; r.f4 = *(const float4*)p; return r; }
__device__ __forceinline__ void st4u(float* p, const F4U a) { *(float4*)p = a.f4; }
__device__ __forceinline__ F4U ld4cg(const float* p) {
  F4U r;
  asm volatile("ld.global.cg.v4.f32 {%0,%1,%2,%3}, [%4];"
               : "=f"(r.v[0]), "=f"(r.v[1]), "=f"(r.v[2]), "=f"(r.v[3]) : "l"(p));
  return r;
}
__device__ __forceinline__ double lddcg(const double* p) {
  double r;
  asm volatile("ld.global.cg.f64 %0, [%1];" : "=d"(r) : "l"(p));
  return r;
}

/* packed fp32x2 ops (Blackwell) */
__device__ __forceinline__ ull fma2(ull a, ull b, ull c) {
  ull d; asm("fma.rn.f32x2 %0, %1, %2, %3;" : "=l"(d) : "l"(a), "l"(b), "l"(c)); return d;
}
__device__ __forceinline__ ull mul2(ull a, ull b) {
  ull d; asm("mul.rn.f32x2 %0, %1, %2;" : "=l"(d) : "l"(a), "l"(b)); return d;
}
__device__ __forceinline__ ull pack2(float x) {
  ull d; asm("mov.b64 %0, {%1, %1};" : "=l"(d) : "f"(x)); return d;
}
__device__ __forceinline__ void unpack2(ull v, float& lo, float& hi) {
  asm("mov.b64 {%0, %1}, %2;" : "=f"(lo), "=f"(hi) : "l"(v));
}
/* fast sin: args O(1..10); abs err ~2^-21, far below 1e-3 tolerance */
__device__ __forceinline__ float fsin(float x) {
  float r; asm("sin.approx.f32 %0, %1;" : "=f"(r) : "f"(x)); return r;
}
/* half-block named barrier (ids 1 and 2) */
__device__ __forceinline__ void barh(int half) {
  asm volatile("bar.sync %0, 256;" :: "r"(half + 1) : "memory");
}

/* 4x4-output 64-k GEMM via fma.rn.f32x2.
   accf[i][j] = sum_k sa[r0+i][k] * W[cbg*4+j][k]
   sW2 layout (validated R3-R6): for k-pair k2 (0..31):
     sW2[k2*128 +      cbg*4 + {0..3}] = {W[4c][2k2],W[4c][2k2+1],W[4c+1][2k2],W[4c+1][2k2+1]}
     sW2[k2*128 + 64 + cbg*4 + {0..3}] = same for j=4c+2, 4c+3 */
__device__ __forceinline__ void gemm4x4(const float* __restrict__ sa,
                                        const float* __restrict__ sW2,
                                        int r0, int cbg, float accf[4][4]) {
  ull acc[4][4];
#pragma unroll
  for (int i = 0; i < 4; ++i)
#pragma unroll
    for (int j = 0; j < 4; ++j) acc[i][j] = 0ull;

  const float* ap = sa + r0 * DDIM;
#pragma unroll
  for (int k4 = 0; k4 < 16; ++k4) {
    ulonglong2 av[4];
#pragma unroll
    for (int i = 0; i < 4; ++i)
      av[i] = *(const ulonglong2*)(ap + i * DDIM + k4 * 4);
#pragma unroll
    for (int hh = 0; hh < 2; ++hh) {
      const int k2 = k4 * 2 + hh;
      ulonglong2 w01 = *(const ulonglong2*)(sW2 + k2 * 128 + cbg * 4);
      ulonglong2 w23 = *(const ulonglong2*)(sW2 + k2 * 128 + 64 + cbg * 4);
#pragma unroll
      for (int i = 0; i < 4; ++i) {
        ull a = hh ? av[i].y : av[i].x;
        acc[i][0] = fma2(a, w01.x, acc[i][0]);
        acc[i][1] = fma2(a, w01.y, acc[i][1]);
        acc[i][2] = fma2(a, w23.x, acc[i][2]);
        acc[i][3] = fma2(a, w23.y, acc[i][3]);
      }
    }
  }
#pragma unroll
  for (int i = 0; i < 4; ++i)
#pragma unroll
    for (int j = 0; j < 4; ++j) {
      float lo, hi; unpack2(acc[i][j], lo, hi);
      accf[i][j] = lo + hi;
    }
}

__global__ void init_kernel() {
  if (threadIdx.x == 0) { g_count = 0u; g_release = 0u; }
  if (threadIdx.x < NSTEPS) g_tctr[threadIdx.x] = 0u;
}

/* ---------------- the whole solve in one persistent kernel ---------------- */
__global__ void __launch_bounds__(NTHR, 1) ode_kernel(const float* __restrict__ x,
                                                      const float* __restrict__ W,
                                                      const float* __restrict__ b,
                                                      float* __restrict__ out) {
  extern __shared__ float sm[];
  float* sb  = sm + OFF_SB;
  float* sW2 = sm + OFF_W2;
  unsigned* sclaim = (unsigned*)(sm + OFF_CLAIM);

  const int tid = threadIdx.x, bid = blockIdx.x;
  const int half = tid >> 8, htid = tid & 255;
  float* smh = sm + OFF_H0 + half * H_STRIDE;
  float* syi = smh + H_SYI;
  float* sk  = smh + H_SK;
  double* red = (double*)(smh + H_RED);

  const int r0  = (htid >> 4) << 2;      /* rows r0..r0+3 */
  const int cbg = htid & 15;             /* cols cbg*4..+3 */
  const int og  = r0 * DDIM + cbg * 4;   /* own base offset */
  const int lane = tid & 31;

  if (tid < 16) st4u(&sb[tid * 4], ld4u(&b[tid * 4]));
  /* repack W into k-pair-major layout */
  for (int p = tid; p < 2048; p += NTHR) {
    const int k2 = p >> 6, j = p & 63;
    const int cbb = j >> 2, jr = j & 3;
    const int pos = k2 * 128 + ((jr >= 2) ? 64 : 0) + cbb * 4 + (jr & 1) * 2;
    sW2[pos]     = W[j * DDIM + 2 * k2];
    sW2[pos + 1] = W[j * DDIM + 2 * k2 + 1];
  }
  __syncthreads();
  const F4U bb = ld4u(&sb[cbg * 4]);

  /* prologue: Ya = x ; Ka = k1 = f(x).  Static tiles per half-worker. */
  for (int t = bid * 2 + half; t < NTILE; t += PBLK * 2) {
    const size_t base = (size_t)t * TSZ;
    for (int i = htid; i < TSZ / 4; i += HTHR) {
      F4U v = ld4u(&x[base + i * 4]);
      st4u(&syi[i * 4], v);
      st4u(&g_Ya[base + i * 4], v);
    }
    barh(half);
    float acc[4][4];
    gemm4x4(syi, sW2, r0, cbg, acc);
#pragma unroll
    for (int r = 0; r < 4; ++r) {
      F4U kv;
#pragma unroll
      for (int j = 0; j < 4; ++j) kv.v[j] = fsin(-(acc[r][j] + bb.v[j]));
      st4u(&g_Ka[base + og + r * DDIM], kv);
    }
    barh(half);
  }

  unsigned nbar = 1;
  __syncthreads();
  if (tid == 0) {
    __threadfence();
    unsigned old = atomicAdd(&g_count, 1u);
    if (old == PBLK - 1) { atomicExch(&g_count, 0u); __threadfence(); atomicExch(&g_release, nbar); }
    else { while (*((volatile unsigned*)&g_release) < nbar) { } }
    __threadfence();
  }
  __syncthreads();

  float t_now = 0.0f, h = 0.01f, h_eff = 0.01f;
  int sel = 0, done = 0;

  const float E0 = (float)(71.0 / 57600.0);
  const float E2 = (float)(-71.0 / 16695.0);
  const float E3 = (float)(71.0 / 1920.0);
  const float E4 = (float)(-17253.0 / 339200.0);
  const float E5 = (float)(22.0 / 525.0);
  const float E6 = (float)(-1.0 / 40.0);
  const float ATOL = 1e-5f, RTOL = 1e-5f;

  for (int step = 0; step < NSTEPS; ++step) {
    if (done) break;
    const float* __restrict__ Yg = sel ? g_Yb : g_Ya;
    const float* __restrict__ Kg = sel ? g_Kb : g_Ka;
    float* __restrict__ Yo = sel ? g_Ya : g_Yb;
    float* __restrict__ Ko = sel ? g_Ka : g_Kb;
    const ull h2 = pack2(h_eff);

    /* ---- work-stealing tile loop (per half-worker) ---- */
    for (;;) {
      if (htid == 0) sclaim[half] = atomicAdd(&g_tctr[step], 1u);
      barh(half);
      const unsigned tt = sclaim[half];
      barh(half);
      if (tt >= NTILE) break;
      const size_t base = (size_t)tt * TSZ;

      /* own y, k1 in registers (loaded once per tile; .cg: L1 may be stale) */
      F4U yq[4], k1r[4], k7r[4];
#pragma unroll
      for (int r = 0; r < 4; ++r) {
        yq[r]  = ld4cg(&Yg[base + og + r * DDIM]);
        k1r[r] = ld4cg(&Kg[base + og + r * DDIM]);
      }

      float acc[4][4];
      for (int st = 1; st <= 6; ++st) {
        const ull c0 = pack2(cA[st - 1][0]);
#pragma unroll
        for (int r = 0; r < 4; ++r) {
          const int o = og + r * DDIM;
          ull s0 = mul2(c0, k1r[r].q[0]);
          ull s1 = mul2(c0, k1r[r].q[1]);
          for (int m = 0; m < st - 1; ++m) {
            const ull cm = pack2(cA[st - 1][m + 1]);
            F4U kv = ld4u(&sk[m * TSZ + o]);
            s0 = fma2(cm, kv.q[0], s0);
            s1 = fma2(cm, kv.q[1], s1);
          }
          F4U yiv;
          yiv.q[0] = fma2(h2, s0, yq[r].q[0]);
          yiv.q[1] = fma2(h2, s1, yq[r].q[1]);
          st4u(&syi[o], yiv);
          if (st == 6) st4u(&Yo[base + o], yiv);   /* candidate y5 */
        }
        barh(half);                 /* syi writes visible */

        gemm4x4(syi, sW2, r0, cbg, acc);

        if (st < 6) {
#pragma unroll
          for (int r = 0; r < 4; ++r) {
            F4U kv;
#pragma unroll
            for (int j = 0; j < 4; ++j) kv.v[j] = fsin(-(acc[r][j] + bb.v[j]));
            st4u(&sk[(st - 1) * TSZ + og + r * DDIM], kv);   /* same-thread slot */
          }
          barh(half);               /* gemm reads done before next combine writes */
        } else {
#pragma unroll
          for (int r = 0; r < 4; ++r)
#pragma unroll
            for (int j = 0; j < 4; ++j) k7r[r].v[j] = fsin(-(acc[r][j] + bb.v[j]));
        }
      }

      /* error accumulation + FSAL k7 -> next k1 (own elements) */
      double lsum = 0.0;
#pragma unroll
      for (int r = 0; r < 4; ++r) {
        const int o = og + r * DDIM;
        F4U k3 = ld4u(&sk[1 * TSZ + o]);
        F4U k4 = ld4u(&sk[2 * TSZ + o]);
        F4U k5 = ld4u(&sk[3 * TSZ + o]);
        F4U k6 = ld4u(&sk[4 * TSZ + o]);
        F4U y5 = ld4u(&syi[o]);            /* self-written */
        st4u(&Ko[base + o], k7r[r]);
#pragma unroll
        for (int j = 0; j < 4; ++j) {
          float e = E0 * k1r[r].v[j];
          e = fmaf(E2, k3.v[j], e);
          e = fmaf(E3, k4.v[j], e);
          e = fmaf(E4, k5.v[j], e);
          e = fmaf(E5, k6.v[j], e);
          e = fmaf(E6, k7r[r].v[j], e);
          e *= h_eff;
          float scale = fmaf(RTOL, fmaxf(fabsf(yq[r].v[j]), fabsf(y5.v[j])), ATOL);
          float rr = e / scale;
          lsum += (double)(rr * rr);
        }
      }
      /* deterministic per-tile reduce: warp shuffle tree + fixed 8-term sum */
#pragma unroll
      for (int off = 16; off > 0; off >>= 1)
        lsum += __shfl_down_sync(0xffffffffu, lsum, off);
      if (lane == 0) red[htid >> 5] = lsum;
      barh(half);
      if (htid == 0) {
        double s = 0.0;
#pragma unroll
        for (int w = 0; w < 8; ++w) s += red[w];
        g_tpart[tt] = s;
        __threadfence();
      }
      barh(half);   /* red reusable; also orders before next claim */
    }

    /* ---- grid barrier ---- */
    ++nbar;
    __syncthreads();
    if (tid == 0) {
      __threadfence();
      unsigned old = atomicAdd(&g_count, 1u);
      if (old == PBLK - 1) { atomicExch(&g_count, 0u); __threadfence(); atomicExch(&g_release, nbar); }
      else { while (*((volatile unsigned*)&g_release) < nbar) { } }
      __threadfence();
    }
    __syncthreads();

    /* ---- deterministic control: fixed-order sum of 1024 tile partials ---- */
    double* sdd = (double*)(sm + OFF_H0 + H_SYI);   /* half0 syi region, 4KB */
    sdd[tid] = lddcg(&g_tpart[2 * tid]) + lddcg(&g_tpart[2 * tid + 1]);
    __syncthreads();
#pragma unroll
    for (int off = NTHR / 2; off > 0; off >>= 1) {
      if (tid < off) sdd[tid] += sdd[tid + off];
      __syncthreads();
    }
    const float err_norm = sqrtf((float)(sdd[0] / (double)((double)NROWS * (double)DDIM)));
    __syncthreads();

    /* exact reference control law (redundant in every thread/block) */
    const int accept = (err_norm <= 1.0f);
    if (accept) { t_now += h_eff; sel ^= 1; }
    float factor = 0.9f * powf(fmaxf(err_norm, 1e-10f), -0.2f);
    factor = fminf(fmaxf(factor, 0.2f), 10.0f);
    h = h_eff * factor;
    const float remaining = 5.0f - t_now;
    done = (remaining <= 0.0f) ? 1 : 0;
    h_eff = fminf(h, fmaxf(remaining, 1e-12f));
  }

  /* write accepted buffer to output (grid-stride, .cg: bypass stale L1) */
  const float* __restrict__ Yf = sel ? g_Yb : g_Ya;
  for (size_t i = (size_t)bid * NTHR + tid; i < (size_t)NROWS * DDIM / 4; i += (size_t)PBLK * NTHR) {
    F4U v = ld4cg(&Yf[i * 4]);
    st4u(&out[i * 4], v);
  }
}

extern "C" void kernel_launch(void* const* d_in, const int* in_sizes, int n_in,
                              void* d_out, int out_size) {
  const float* x = (const float*)d_in[0];
  const float* W = (const float*)d_in[1];
  const float* b = (const float*)d_in[2];
  float* out = (float*)d_out;

  cudaFuncSetAttribute(ode_kernel, cudaFuncAttributeMaxDynamicSharedMemorySize, SMEM_BYTES);

  init_kernel<<<1, 128>>>();
  ode_kernel<<<PBLK, NTHR, SMEM_BYTES>>>(x, W, b, out);
}

// round 8
// speedup vs baseline: 1.2259x; 1.0156x over previous
#include <cuda_runtime.h>
#include <math.h>

#define NROWS   65536
#define DDIM    64
#define NTILE   1024          /* NROWS / 64 */
#define PBLK    148           /* persistent blocks, 1 per SM */
#define NTHR    512
#define HTHR    256           /* half-block worker size */
#define NSTEPS  128
#define TSZ     4096          /* 64*64 floats per tile */

/* shared memory layout (float offsets) */
#define OFF_SB    0            /* 64 : bias */
#define OFF_CLAIM 64           /* 2 unsigned claim slots (+pad) */
#define OFF_W2    80           /* 4096 : W repacked */
#define OFF_H0    4176         /* per-half regions */
#define H_SYI0    0
#define H_SYI1    4096
#define H_SK      8192         /* 4 slots (k3..k6) x 4096 */
#define H_RED     24576        /* 8 doubles */
#define H_STRIDE  24592
#define SMEM_FLOATS (OFF_H0 + 2 * H_STRIDE)
#define SMEM_BYTES  (SMEM_FLOATS * 4)

typedef unsigned long long ull;

/* ---------------- persistent device state (no allocations) ---------------- */
__device__ float    g_Ya[NROWS * DDIM];
__device__ float    g_Yb[NROWS * DDIM];
__device__ float    g_Ka[NROWS * DDIM];
__device__ float    g_Kb[NROWS * DDIM];
__device__ double   g_tpart[NTILE];       /* per-tile error partials (deterministic) */
__device__ unsigned g_tctr[NSTEPS];       /* per-step work-steal counters */
__device__ unsigned g_count;
__device__ unsigned g_release;

/* Dormand-Prince A coefficients (exact float32 of rationals) */
__constant__ float cA[6][6] = {
  { (float)(1.0/5.0), 0.f, 0.f, 0.f, 0.f, 0.f },
  { (float)(3.0/40.0), (float)(9.0/40.0), 0.f, 0.f, 0.f, 0.f },
  { (float)(44.0/45.0), (float)(-56.0/15.0), (float)(32.0/9.0), 0.f, 0.f, 0.f },
  { (float)(19372.0/6561.0), (float)(-25360.0/2187.0), (float)(64448.0/6561.0), (float)(-212.0/729.0), 0.f, 0.f },
  { (float)(9017.0/3168.0), (float)(-355.0/33.0), (float)(46732.0/5247.0), (float)(49.0/176.0), (float)(-5103.0/18656.0), 0.f },
  { (float)(35.0/384.0), 0.f, (float)(500.0/1113.0), (float)(125.0/192.0), (float)(-2187.0/6784.0), (float)(11.0/84.0) },
};

union F4U {
  float v[4];
  ull   q[2];
  float4 f4;
};

__device__ __forceinline__ F4U ld4u(const float* p) { F4U r; r.f4 = *(const float4*)p; return r; }
__device__ __forceinline__ void st4u(float* p, const F4U a) { *(float4*)p = a.f4; }
__device__ __forceinline__ F4U ld4cg(const float* p) {
  F4U r;
  asm volatile("ld.global.cg.v4.f32 {%0,%1,%2,%3}, [%4];"
               : "=f"(r.v[0]), "=f"(r.v[1]), "=f"(r.v[2]), "=f"(r.v[3]) : "l"(p));
  return r;
}
__device__ __forceinline__ double lddcg(const double* p) {
  double r;
  asm volatile("ld.global.cg.f64 %0, [%1];" : "=d"(r) : "l"(p));
  return r;
}

/* packed fp32x2 ops (Blackwell) */
__device__ __forceinline__ ull fma2(ull a, ull b, ull c) {
  ull d; asm("fma.rn.f32x2 %0, %1, %2, %3;" : "=l"(d) : "l"(a), "l"(b), "l"(c)); return d;
}
__device__ __forceinline__ ull mul2(ull a, ull b) {
  ull d; asm("mul.rn.f32x2 %0, %1, %2;" : "=l"(d) : "l"(a), "l"(b)); return d;
}
__device__ __forceinline__ ull pack2(float x) {
  ull d; asm("mov.b64 %0, {%1, %1};" : "=l"(d) : "f"(x)); return d;
}
__device__ __forceinline__ void unpack2(ull v, float& lo, float& hi) {
  asm("mov.b64 {%0, %1}, %2;" : "=f"(lo), "=f"(hi) : "l"(v));
}
/* fast sin: args O(1..10); abs err ~2^-21, far below 1e-3 tolerance */
__device__ __forceinline__ float fsin(float x) {
  float r; asm("sin.approx.f32 %0, %1;" : "=f"(r) : "f"(x)); return r;
}
/* half-block named barrier (ids 1 and 2) */
__device__ __forceinline__ void barh(int half) {
  asm volatile("bar.sync %0, 256;" :: "r"(half + 1) : "memory");
}

/* 4x4-output 64-k GEMM via fma.rn.f32x2 (layout validated R3-R7). */
__device__ __forceinline__ void gemm4x4(const float* __restrict__ sa,
                                        const float* __restrict__ sW2,
                                        int r0, int cbg, float accf[4][4]) {
  ull acc[4][4];
#pragma unroll
  for (int i = 0; i < 4; ++i)
#pragma unroll
    for (int j = 0; j < 4; ++j) acc[i][j] = 0ull;

  const float* ap = sa + r0 * DDIM;
#pragma unroll
  for (int k4 = 0; k4 < 16; ++k4) {
    ulonglong2 av[4];
#pragma unroll
    for (int i = 0; i < 4; ++i)
      av[i] = *(const ulonglong2*)(ap + i * DDIM + k4 * 4);
#pragma unroll
    for (int hh = 0; hh < 2; ++hh) {
      const int k2i = k4 * 2 + hh;
      ulonglong2 w01 = *(const ulonglong2*)(sW2 + k2i * 128 + cbg * 4);
      ulonglong2 w23 = *(const ulonglong2*)(sW2 + k2i * 128 + 64 + cbg * 4);
#pragma unroll
      for (int i = 0; i < 4; ++i) {
        ull a = hh ? av[i].y : av[i].x;
        acc[i][0] = fma2(a, w01.x, acc[i][0]);
        acc[i][1] = fma2(a, w01.y, acc[i][1]);
        acc[i][2] = fma2(a, w23.x, acc[i][2]);
        acc[i][3] = fma2(a, w23.y, acc[i][3]);
      }
    }
  }
#pragma unroll
  for (int i = 0; i < 4; ++i)
#pragma unroll
    for (int j = 0; j < 4; ++j) {
      float lo, hi; unpack2(acc[i][j], lo, hi);
      accf[i][j] = lo + hi;
    }
}

__global__ void init_kernel() {
  if (threadIdx.x == 0) { g_count = 0u; g_release = 0u; }
  if (threadIdx.x < NSTEPS) g_tctr[threadIdx.x] = 0u;
}

/* ---------------- the whole solve in one persistent kernel ---------------- */
__global__ void __launch_bounds__(NTHR, 1) ode_kernel(const float* __restrict__ x,
                                                      const float* __restrict__ W,
                                                      const float* __restrict__ b,
                                                      float* __restrict__ out) {
  extern __shared__ float sm[];
  float* sb  = sm + OFF_SB;
  float* sW2 = sm + OFF_W2;
  unsigned* sclaim = (unsigned*)(sm + OFF_CLAIM);

  const int tid = threadIdx.x, bid = blockIdx.x;
  const int half = tid >> 8, htid = tid & 255;
  float* smh  = sm + OFF_H0 + half * H_STRIDE;
  float* syi0 = smh + H_SYI0;
  float* syi1 = smh + H_SYI1;
  float* sk   = smh + H_SK;          /* slots: 0=k3 1=k4 2=k5 3=k6 */
  double* red = (double*)(smh + H_RED);

  const int r0  = (htid >> 4) << 2;      /* rows r0..r0+3 */
  const int cbg = htid & 15;             /* cols cbg*4..+3 */
  const int og  = r0 * DDIM + cbg * 4;   /* own base offset */
  const int lane = tid & 31;

  if (tid < 16) st4u(&sb[tid * 4], ld4u(&b[tid * 4]));
  /* repack W into k-pair-major layout */
  for (int p = tid; p < 2048; p += NTHR) {
    const int k2i = p >> 6, j = p & 63;
    const int cbb = j >> 2, jr = j & 3;
    const int pos = k2i * 128 + ((jr >= 2) ? 64 : 0) + cbb * 4 + (jr & 1) * 2;
    sW2[pos]     = W[j * DDIM + 2 * k2i];
    sW2[pos + 1] = W[j * DDIM + 2 * k2i + 1];
  }
  __syncthreads();
  const F4U bb = ld4u(&sb[cbg * 4]);

  /* prologue: Ya = x ; Ka = k1 = f(x).  Static tiles per half-worker. */
  for (int t = bid * 2 + half; t < NTILE; t += PBLK * 2) {
    const size_t base = (size_t)t * TSZ;
    for (int i = htid; i < TSZ / 4; i += HTHR) {
      F4U v = ld4u(&x[base + i * 4]);
      st4u(&syi0[i * 4], v);
      st4u(&g_Ya[base + i * 4], v);
    }
    barh(half);
    float acc[4][4];
    gemm4x4(syi0, sW2, r0, cbg, acc);
#pragma unroll
    for (int r = 0; r < 4; ++r) {
      F4U kv;
#pragma unroll
      for (int j = 0; j < 4; ++j) kv.v[j] = fsin(-(acc[r][j] + bb.v[j]));
      st4u(&g_Ka[base + og + r * DDIM], kv);
    }
    barh(half);
  }

  unsigned nbar = 1;
  __syncthreads();
  if (tid == 0) {
    __threadfence();
    unsigned old = atomicAdd(&g_count, 1u);
    if (old == PBLK - 1) { atomicExch(&g_count, 0u); __threadfence(); atomicExch(&g_release, nbar); }
    else { while (*((volatile unsigned*)&g_release) < nbar) { } }
    __threadfence();
  }
  __syncthreads();

  float t_now = 0.0f, h = 0.01f, h_eff = 0.01f;
  int sel = 0, done = 0;

  const float E0 = (float)(71.0 / 57600.0);
  const float E2 = (float)(-71.0 / 16695.0);
  const float E3 = (float)(71.0 / 1920.0);
  const float E4 = (float)(-17253.0 / 339200.0);
  const float E5 = (float)(22.0 / 525.0);
  const float E6 = (float)(-1.0 / 40.0);
  const float ATOL = 1e-5f, RTOL = 1e-5f;

  for (int step = 0; step < NSTEPS; ++step) {
    if (done) break;
    const float* __restrict__ Yg = sel ? g_Yb : g_Ya;
    const float* __restrict__ Kg = sel ? g_Kb : g_Ka;
    float* __restrict__ Yo = sel ? g_Ya : g_Yb;
    float* __restrict__ Ko = sel ? g_Ka : g_Kb;
    const ull h2 = pack2(h_eff);

    /* ---- work-stealing tile loop (per half-worker) ---- */
    if (htid == 0) sclaim[half] = atomicAdd(&g_tctr[step], 1u);
    barh(half);
    unsigned tt = sclaim[half];
    barh(half);

    while (tt < NTILE) {
      const size_t base = (size_t)tt * TSZ;

      /* own y, k1, k2 in registers */
      F4U yq[4], k1r[4], k2r[4], y5r[4], eac[4];
#pragma unroll
      for (int r = 0; r < 4; ++r) {
        yq[r]  = ld4cg(&Yg[base + og + r * DDIM]);
        k1r[r] = ld4cg(&Kg[base + og + r * DDIM]);
      }

      float acc[4][4];
      /* ---- stages 1..5 (rolled; one barrier per stage) ---- */
      for (int st = 1; st <= 5; ++st) {
        float* syiW = (st & 1) ? syi1 : syi0;
        const ull c0 = pack2(cA[st - 1][0]);
        const ull c1 = pack2(cA[st - 1][1]);
#pragma unroll
        for (int r = 0; r < 4; ++r) {
          const int o = og + r * DDIM;
          ull s0 = mul2(c0, k1r[r].q[0]);
          ull s1 = mul2(c0, k1r[r].q[1]);
          if (st >= 2) {                      /* k2 from registers */
            s0 = fma2(c1, k2r[r].q[0], s0);
            s1 = fma2(c1, k2r[r].q[1], s1);
          }
          for (int m = 0; m < st - 2; ++m) {  /* k3..k_st from smem */
            const ull cm = pack2(cA[st - 1][m + 2]);
            F4U kv = ld4u(&sk[m * TSZ + o]);
            s0 = fma2(cm, kv.q[0], s0);
            s1 = fma2(cm, kv.q[1], s1);
          }
          F4U yiv;
          yiv.q[0] = fma2(h2, s0, yq[r].q[0]);
          yiv.q[1] = fma2(h2, s1, yq[r].q[1]);
          st4u(&syiW[o], yiv);
        }
        barh(half);                /* single barrier: syi writes visible */

        gemm4x4(syiW, sW2, r0, cbg, acc);

        if (st == 1) {
#pragma unroll
          for (int r = 0; r < 4; ++r)
#pragma unroll
            for (int j = 0; j < 4; ++j) k2r[r].v[j] = fsin(-(acc[r][j] + bb.v[j]));
        } else {
#pragma unroll
          for (int r = 0; r < 4; ++r) {
            F4U kv;
#pragma unroll
            for (int j = 0; j < 4; ++j) kv.v[j] = fsin(-(acc[r][j] + bb.v[j]));
            st4u(&sk[(st - 2) * TSZ + og + r * DDIM], kv);   /* same-thread slot */
          }
        }
        /* no second barrier: double-buffered syi covers the WAR hazard */
      }

      /* ---- stage 6 (peeled, fused with error accumulation) ---- */
      {
        const ull C1 = pack2((float)(35.0 / 384.0));
        const ull C3 = pack2((float)(500.0 / 1113.0));
        const ull C4 = pack2((float)(125.0 / 192.0));
        const ull C5 = pack2((float)(-2187.0 / 6784.0));
        const ull C6 = pack2((float)(11.0 / 84.0));
        const ull F0 = pack2(E0), F2 = pack2(E2), F3 = pack2(E3);
        const ull F4c = pack2(E4), F5 = pack2(E5);
#pragma unroll
        for (int r = 0; r < 4; ++r) {
          const int o = og + r * DDIM;
          F4U k3 = ld4u(&sk[0 * TSZ + o]);
          F4U k4 = ld4u(&sk[1 * TSZ + o]);
          F4U k5 = ld4u(&sk[2 * TSZ + o]);
          F4U k6 = ld4u(&sk[3 * TSZ + o]);
#pragma unroll
          for (int q = 0; q < 2; ++q) {
            ull s = mul2(C1, k1r[r].q[q]);       /* B5: k2 coeff = 0 */
            s = fma2(C3, k3.q[q], s);
            s = fma2(C4, k4.q[q], s);
            s = fma2(C5, k5.q[q], s);
            s = fma2(C6, k6.q[q], s);
            y5r[r].q[q] = fma2(h2, s, yq[r].q[q]);
            ull e = mul2(F0, k1r[r].q[q]);       /* E1 = 0 */
            e = fma2(F2, k3.q[q], e);
            e = fma2(F3, k4.q[q], e);
            e = fma2(F4c, k5.q[q], e);
            e = fma2(F5, k6.q[q], e);
            eac[r].q[q] = e;
          }
          st4u(&syi0[o], y5r[r]);                /* y5 is stage-6 input (FSAL) */
          st4u(&Yo[base + o], y5r[r]);           /* candidate y5 out */
        }
        barh(half);

        gemm4x4(syi0, sW2, r0, cbg, acc);
      }

      /* k7 + error finalize + FSAL */
      double lsum = 0.0;
#pragma unroll
      for (int r = 0; r < 4; ++r) {
        const int o = og + r * DDIM;
        F4U k7;
#pragma unroll
        for (int j = 0; j < 4; ++j) k7.v[j] = fsin(-(acc[r][j] + bb.v[j]));
        st4u(&Ko[base + o], k7);
#pragma unroll
        for (int j = 0; j < 4; ++j) {
          float e = fmaf(E6, k7.v[j], eac[r].v[j]);
          e *= h_eff;
          float scale = fmaf(RTOL, fmaxf(fabsf(yq[r].v[j]), fabsf(y5r[r].v[j])), ATOL);
          float rr = e / scale;
          lsum += (double)(rr * rr);
        }
      }

      /* claim next tile (free: folded into epilogue barrier) */
      if (htid == 0) sclaim[half] = atomicAdd(&g_tctr[step], 1u);

      /* deterministic per-tile reduce */
#pragma unroll
      for (int off = 16; off > 0; off >>= 1)
        lsum += __shfl_down_sync(0xffffffffu, lsum, off);
      if (lane == 0) red[htid >> 5] = lsum;
      barh(half);
      unsigned nx = sclaim[half];
      if (htid == 0) {
        double s = 0.0;
#pragma unroll
        for (int w = 0; w < 8; ++w) s += red[w];
        g_tpart[tt] = s;
        __threadfence();
      }
      barh(half);
      tt = nx;
    }

    /* ---- grid barrier ---- */
    ++nbar;
    __syncthreads();
    if (tid == 0) {
      __threadfence();
      unsigned old = atomicAdd(&g_count, 1u);
      if (old == PBLK - 1) { atomicExch(&g_count, 0u); __threadfence(); atomicExch(&g_release, nbar); }
      else { while (*((volatile unsigned*)&g_release) < nbar) { } }
      __threadfence();
    }
    __syncthreads();

    /* ---- deterministic control: fixed-order sum of 1024 tile partials ---- */
    double* sdd = (double*)(sm + OFF_H0 + H_SYI0);   /* half0 syi0 region */
    sdd[tid] = lddcg(&g_tpart[2 * tid]) + lddcg(&g_tpart[2 * tid + 1]);
    __syncthreads();
#pragma unroll
    for (int off = NTHR / 2; off > 0; off >>= 1) {
      if (tid < off) sdd[tid] += sdd[tid + off];
      __syncthreads();
    }
    const float err_norm = sqrtf((float)(sdd[0] / (double)((double)NROWS * (double)DDIM)));
    __syncthreads();

    /* exact reference control law (redundant in every thread/block) */
    const int accept = (err_norm <= 1.0f);
    if (accept) { t_now += h_eff; sel ^= 1; }
    float factor = 0.9f * powf(fmaxf(err_norm, 1e-10f), -0.2f);
    factor = fminf(fmaxf(factor, 0.2f), 10.0f);
    h = h_eff * factor;
    const float remaining = 5.0f - t_now;
    done = (remaining <= 0.0f) ? 1 : 0;
    h_eff = fminf(h, fmaxf(remaining, 1e-12f));
  }

  /* write accepted buffer to output (grid-stride, .cg: bypass stale L1) */
  const float* __restrict__ Yf = sel ? g_Yb : g_Ya;
  for (size_t i = (size_t)bid * NTHR + tid; i < (size_t)NROWS * DDIM / 4; i += (size_t)PBLK * NTHR) {
    F4U v = ld4cg(&Yf[i * 4]);
    st4u(&out[i * 4], v);
  }
}

extern "C" void kernel_launch(void* const* d_in, const int* in_sizes, int n_in,
                              void* d_out, int out_size) {
  const float* x = (const float*)d_in[0];
  const float* W = (const float*)d_in[1];
  const float* b = (const float*)d_in[2];
  float* out = (float*)d_out;

  cudaFuncSetAttribute(ode_kernel, cudaFuncAttributeMaxDynamicSharedMemorySize, SMEM_BYTES);

  init_kernel<<<1, 128>>>();
  ode_kernel<<<PBLK, NTHR, SMEM_BYTES>>>(x, W, b, out);
}